// round 15
// baseline (speedup 1.0000x reference)
#include <cuda_runtime.h>
#include <cuda_bf16.h>
#include <cstdint>

#define K_DIM   8192
#define B_DIM   256
#define OUT_DIM 8192
#define BM      128
#define BN      128
#define KC      32
#define NT      (K_DIM / KC)          // 256 stages
#define RSTRIDE 80                    // bytes per smem row (32 bf16 + 16B pad)
#define SPLIT_BYTES (128 * RSTRIDE)   // 10240 per split tile
#define STAGE_BYTES (4 * SPLIT_BYTES) // A_hi|A_lo|B_hi|B_lo = 40960
#define NSTAGE  3
#define LH_OFF  (NSTAGE * STAGE_BYTES)        // 122880: low[8192] | high[8192]
#define DSMEM_BYTES (LH_OFF + 2 * K_DIM * 4)  // 188416

// ---------------- scratch: bf16 split of x ----------------
__device__ __nv_bfloat16 g_x_hi[(size_t)B_DIM * K_DIM];
__device__ __nv_bfloat16 g_x_lo[(size_t)B_DIM * K_DIM];

// ---------------- helpers ----------------
__device__ __forceinline__ uint32_t smem_u32(const void* p) {
    uint32_t a;
    asm("{ .reg .u64 t; cvta.to.shared.u64 t, %1; cvt.u32.u64 %0, t; }" : "=r"(a) : "l"(p));
    return a;
}
__device__ __forceinline__ uint32_t cvt2(float hiVal, float loVal) {
    uint32_t r;
    asm("cvt.rn.bf16x2.f32 %0, %1, %2;" : "=r"(r) : "f"(hiVal), "f"(loVal));
    return r;
}

#define LDSM4(r0, r1, r2, r3, addr) \
    asm volatile("ldmatrix.sync.aligned.m8n8.x4.shared.b16 {%0,%1,%2,%3}, [%4];" \
                 : "=r"(r0), "=r"(r1), "=r"(r2), "=r"(r3) : "r"(addr))

#define MMA(c, a, b) \
    asm volatile("mma.sync.aligned.m16n8k16.row.col.f32.bf16.bf16.f32 " \
                 "{%0,%1,%2,%3}, {%4,%5,%6,%7}, {%8,%9}, {%0,%1,%2,%3};" \
                 : "+f"((c)[0]), "+f"((c)[1]), "+f"((c)[2]), "+f"((c)[3]) \
                 : "r"((a)[0]), "r"((a)[1]), "r"((a)[2]), "r"((a)[3]), \
                   "r"((b)[0]), "r"((b)[1]))

#define CP_ASYNC16(dst, src) \
    asm volatile("cp.async.cg.shared.global [%0], [%1], 16;" :: "r"(dst), "l"(src) : "memory")
#define CP_COMMIT() asm volatile("cp.async.commit_group;" ::: "memory")
#define CP_WAIT1()  asm volatile("cp.async.wait_group 1;" ::: "memory")
#define CP_WAIT0()  asm volatile("cp.async.wait_group 0;" ::: "memory")

// ---------------- kernel 1: split x into bf16 hi/lo ----------------
__global__ __launch_bounds__(256)
void convert_x_kernel(const float* __restrict__ x) {
    size_t i = ((size_t)blockIdx.x * 256 + threadIdx.x) * 8;
    float4 a = *reinterpret_cast<const float4*>(x + i);
    float4 b = *reinterpret_cast<const float4*>(x + i + 4);
    uint32_t h0 = cvt2(a.y, a.x), h1 = cvt2(a.w, a.z);
    uint32_t h2 = cvt2(b.y, b.x), h3 = cvt2(b.w, b.z);
    float l0 = a.x - __uint_as_float(h0 << 16);
    float l1 = a.y - __uint_as_float(h0 & 0xffff0000u);
    float l2 = a.z - __uint_as_float(h1 << 16);
    float l3 = a.w - __uint_as_float(h1 & 0xffff0000u);
    float l4 = b.x - __uint_as_float(h2 << 16);
    float l5 = b.y - __uint_as_float(h2 & 0xffff0000u);
    float l6 = b.z - __uint_as_float(h3 << 16);
    float l7 = b.w - __uint_as_float(h3 & 0xffff0000u);
    *reinterpret_cast<uint4*>(g_x_hi + i) = make_uint4(h0, h1, h2, h3);
    *reinterpret_cast<uint4*>(g_x_lo + i) =
        make_uint4(cvt2(l1, l0), cvt2(l3, l2), cvt2(l5, l4), cvt2(l7, l6));
}

// ---------------- kernel 2: split-bf16 mma GEMM + fused IBP ----------------
__global__ __launch_bounds__(256, 1)
void abstract_linear_mma_kernel(const float* __restrict__ low,
                                const float* __restrict__ high,
                                const float* __restrict__ W,
                                const float* __restrict__ bias,
                                float* __restrict__ y,
                                float* __restrict__ low_out,
                                float* __restrict__ high_out)
{
    extern __shared__ __align__(128) char dsm[];
    const uint32_t sbase = smem_u32(dsm);

    const int tid  = threadIdx.x;
    const int lane = tid & 31;
    const int wid  = tid >> 5;       // 0..7
    const int nBase = blockIdx.x * BN;
    const int mBase = blockIdx.y * BM;
    const bool doB = (blockIdx.y == 0);

    const int wm = wid >> 2;   // 0..1  (m direction, 64 rows each)
    const int wn = wid & 3;    // 0..3  (n direction, 32 cols each)

    // ---- preload low/high into smem (used by doB CTAs) ----
    float* s_low  = reinterpret_cast<float*>(dsm + LH_OFF);
    float* s_high = s_low + K_DIM;
    if (doB) {
        #pragma unroll
        for (int i = 0; i < 8; ++i) {
            const int idx = (tid + i * 256) * 4;
            *reinterpret_cast<float4*>(s_low + idx)  = *reinterpret_cast<const float4*>(low + idx);
            *reinterpret_cast<float4*>(s_high + idx) = *reinterpret_cast<const float4*>(high + idx);
        }
    }
    __syncthreads();   // preload visible before first stashW (race fix)

    // ---- x loader (cp.async): thread -> (split, row): 64B per thread ----
    const int xrow = tid & 127;
    const bool isHi = (tid < 128);
    const __nv_bfloat16* xg = (isHi ? g_x_hi : g_x_lo) + (size_t)(mBase + xrow) * K_DIM;
    const uint32_t xdstBase = (isHi ? 0u : (uint32_t)SPLIT_BYTES) + (uint32_t)xrow * RSTRIDE;

    // ---- W loader: thread -> (row, 16-elem k half) ----
    const int wrow = tid >> 1;        // 0..127
    const int lkh  = tid & 1;         // k half (16 elems)
    const float* wg = W + (size_t)(nBase + wrow) * K_DIM + lkh * 16;
    const uint32_t wsts = (uint32_t)wrow * RSTRIDE + lkh * 32;

    // ---- ldmatrix per-thread offsets ----
    const uint32_t aOff = (uint32_t)(wm * 64 + (lane & 15)) * RSTRIDE + (lane >> 4) * 16;
    const uint32_t bOff = (uint32_t)(wn * 32 + (lane & 7) + ((lane >> 4) & 1) * 8) * RSTRIDE
                        + ((lane >> 3) & 1) * 16;

    float acc[4][4][4];
    #pragma unroll
    for (int i = 0; i < 4; ++i)
        #pragma unroll
        for (int j = 0; j < 4; ++j)
            #pragma unroll
            for (int r = 0; r < 4; ++r) acc[i][j][r] = 0.f;

    float boundLo = 0.f, boundHi = 0.f;
    float4 wv[2][4];   // double-buffered: loadW can issue before stashW consumes

    auto cpX = [&](int stage, int kt) {
        const uint32_t dst = sbase + stage * STAGE_BYTES + xdstBase;
        const __nv_bfloat16* src = xg + kt * KC;
        CP_ASYNC16(dst,      src);
        CP_ASYNC16(dst + 16, src + 8);
        CP_ASYNC16(dst + 32, src + 16);
        CP_ASYNC16(dst + 48, src + 24);
        CP_COMMIT();
    };

    auto loadW = [&](int kt, int buf) {
        #pragma unroll
        for (int i = 0; i < 4; ++i)
            wv[buf][i] = *reinterpret_cast<const float4*>(wg + (size_t)kt * KC + i * 4);
    };

    auto stashW = [&](int stage, int kt, int buf) {
        char* bHp = dsm + (size_t)stage * STAGE_BYTES + 2 * SPLIT_BYTES + wsts;
        char* bLp = bHp + SPLIT_BYTES;
        #pragma unroll
        for (int i = 0; i < 2; ++i) {
            const float4 a = wv[buf][2 * i], b = wv[buf][2 * i + 1];
            uint32_t h0 = cvt2(a.y, a.x), h1 = cvt2(a.w, a.z);
            uint32_t h2 = cvt2(b.y, b.x), h3 = cvt2(b.w, b.z);
            float l0 = a.x - __uint_as_float(h0 << 16);
            float l1 = a.y - __uint_as_float(h0 & 0xffff0000u);
            float l2 = a.z - __uint_as_float(h1 << 16);
            float l3 = a.w - __uint_as_float(h1 & 0xffff0000u);
            float l4 = b.x - __uint_as_float(h2 << 16);
            float l5 = b.y - __uint_as_float(h2 & 0xffff0000u);
            float l6 = b.z - __uint_as_float(h3 << 16);
            float l7 = b.w - __uint_as_float(h3 & 0xffff0000u);
            *reinterpret_cast<uint4*>(bHp + i * 16) = make_uint4(h0, h1, h2, h3);
            *reinterpret_cast<uint4*>(bLp + i * 16) =
                make_uint4(cvt2(l1, l0), cvt2(l3, l2), cvt2(l5, l4), cvt2(l7, l6));
            if (doB) {
                const float* lp = s_low  + kt * KC + lkh * 16 + i * 8;
                const float* hp = s_high + kt * KC + lkh * 16 + i * 8;
                const float4 la = *reinterpret_cast<const float4*>(lp);
                const float4 lb = *reinterpret_cast<const float4*>(lp + 4);
                const float4 ha = *reinterpret_cast<const float4*>(hp);
                const float4 hb = *reinterpret_cast<const float4*>(hp + 4);
                float p, q;
                p = a.x * la.x; q = a.x * ha.x; boundLo += fminf(p, q); boundHi += fmaxf(p, q);
                p = a.y * la.y; q = a.y * ha.y; boundLo += fminf(p, q); boundHi += fmaxf(p, q);
                p = a.z * la.z; q = a.z * ha.z; boundLo += fminf(p, q); boundHi += fmaxf(p, q);
                p = a.w * la.w; q = a.w * ha.w; boundLo += fminf(p, q); boundHi += fmaxf(p, q);
                p = b.x * lb.x; q = b.x * hb.x; boundLo += fminf(p, q); boundHi += fmaxf(p, q);
                p = b.y * lb.y; q = b.y * hb.y; boundLo += fminf(p, q); boundHi += fmaxf(p, q);
                p = b.z * lb.z; q = b.z * hb.z; boundLo += fminf(p, q); boundHi += fmaxf(p, q);
                p = b.w * lb.w; q = b.w * hb.w; boundLo += fminf(p, q); boundHi += fmaxf(p, q);
            }
        }
    };

    // software-pipelined fragment loads: k16=1 A-frags load between k16=0 term groups
    auto doMMA = [&](int stage) {
        const uint32_t A_hi = sbase + stage * STAGE_BYTES;
        const uint32_t A_lo = A_hi + SPLIT_BYTES;
        const uint32_t B_hi = A_hi + 2 * SPLIT_BYTES;
        const uint32_t B_lo = A_hi + 3 * SPLIT_BYTES;

        uint32_t aH[2][4][4], aL[2][4][4], bH[2][4][2], bL[2][4][2];

        auto loadA = [&](int k16) {
            #pragma unroll
            for (int mf = 0; mf < 4; ++mf) {
                LDSM4(aH[k16][mf][0], aH[k16][mf][1], aH[k16][mf][2], aH[k16][mf][3],
                      A_hi + aOff + mf * (16 * RSTRIDE) + k16 * 32);
                LDSM4(aL[k16][mf][0], aL[k16][mf][1], aL[k16][mf][2], aL[k16][mf][3],
                      A_lo + aOff + mf * (16 * RSTRIDE) + k16 * 32);
            }
        };
        auto loadB = [&](int k16) {
            #pragma unroll
            for (int p = 0; p < 2; ++p) {
                uint32_t r0, r1, r2, r3;
                LDSM4(r0, r1, r2, r3, B_hi + bOff + p * (16 * RSTRIDE) + k16 * 32);
                bH[k16][2 * p][0] = r0; bH[k16][2 * p][1] = r1;
                bH[k16][2 * p + 1][0] = r2; bH[k16][2 * p + 1][1] = r3;
                LDSM4(r0, r1, r2, r3, B_lo + bOff + p * (16 * RSTRIDE) + k16 * 32);
                bL[k16][2 * p][0] = r0; bL[k16][2 * p][1] = r1;
                bL[k16][2 * p + 1][0] = r2; bL[k16][2 * p + 1][1] = r3;
            }
        };
        auto term = [&](int k16, int t) {
            if (t == 0) {
                #pragma unroll
                for (int mf = 0; mf < 4; ++mf)
                    #pragma unroll
                    for (int nf = 0; nf < 4; ++nf) MMA(acc[mf][nf], aH[k16][mf], bH[k16][nf]);
            } else if (t == 1) {
                #pragma unroll
                for (int mf = 0; mf < 4; ++mf)
                    #pragma unroll
                    for (int nf = 0; nf < 4; ++nf) MMA(acc[mf][nf], aH[k16][mf], bL[k16][nf]);
            } else {
                #pragma unroll
                for (int mf = 0; mf < 4; ++mf)
                    #pragma unroll
                    for (int nf = 0; nf < 4; ++nf) MMA(acc[mf][nf], aL[k16][mf], bH[k16][nf]);
            }
        };

        loadA(0); loadB(0);
        term(0, 0);
        loadA(1);            // hide k16=1 A LDSM under k16=0 MMAs
        term(0, 1);
        loadB(1);            // hide k16=1 B LDSM under k16=0 MMAs
        term(0, 2);
        term(1, 0);
        term(1, 1);
        term(1, 2);
    };

    // ---- prologue ----
    cpX(0, 0);
    cpX(1, 1);
    loadW(0, 0);
    stashW(0, 0, 0);
    loadW(1, 1);
    CP_WAIT1();
    __syncthreads();

    // ---- main loop: cp(kt+2) -> loadW(kt+2) -> stash(kt+1) -> MMA(kt) ----
    #pragma unroll 1
    for (int kt = 0; kt < NT; ++kt) {
        const int stage = kt % NSTAGE;
        const int cur  = (kt + 1) & 1;   // wv buffer holding W(kt+1)
        const int nxt  = kt & 1;         // wv buffer to receive W(kt+2)
        if (kt + 2 < NT) {
            cpX((kt + 2) % NSTAGE, kt + 2);   // async x: issue first
            loadW(kt + 2, nxt);               // W LDG issues before stash block
        }
        if (kt + 1 < NT) stashW((kt + 1) % NSTAGE, kt + 1, cur);
        doMMA(stage);
        if (kt + 2 < NT) { CP_WAIT1(); } else { CP_WAIT0(); }
        __syncthreads();
    }

    // ---- epilogue: y = acc + bias ----
    #pragma unroll
    for (int mf = 0; mf < 4; ++mf) {
        const int r0 = mBase + wm * 64 + mf * 16 + (lane >> 2);
        #pragma unroll
        for (int nf = 0; nf < 4; ++nf) {
            const int c = nBase + wn * 32 + nf * 8 + (lane & 3) * 2;
            const float2 bv = *reinterpret_cast<const float2*>(bias + c);
            float2 o0 = make_float2(acc[mf][nf][0] + bv.x, acc[mf][nf][1] + bv.y);
            float2 o1 = make_float2(acc[mf][nf][2] + bv.x, acc[mf][nf][3] + bv.y);
            *reinterpret_cast<float2*>(y + (size_t)r0 * OUT_DIM + c) = o0;
            *reinterpret_cast<float2*>(y + (size_t)(r0 + 8) * OUT_DIM + c) = o1;
        }
    }

    // ---- epilogue: bounds (width-2 deterministic reduction) ----
    if (doB) {
        boundLo += __shfl_xor_sync(0xffffffffu, boundLo, 1);
        boundHi += __shfl_xor_sync(0xffffffffu, boundHi, 1);
        if (lkh == 0) {
            const int r = nBase + wrow;
            const float bb = bias[r];
            low_out[r]  = boundLo + bb;
            high_out[r] = boundHi + bb;
        }
    }
}

extern "C" void kernel_launch(void* const* d_in, const int* in_sizes, int n_in,
                              void* d_out, int out_size) {
    const float* x    = (const float*)d_in[0];
    const float* low  = (const float*)d_in[1];
    const float* high = (const float*)d_in[2];
    const float* W    = (const float*)d_in[3];
    const float* bias = (const float*)d_in[4];

    float* y        = (float*)d_out;
    float* low_out  = y + (size_t)B_DIM * OUT_DIM;
    float* high_out = low_out + OUT_DIM;

    cudaFuncSetAttribute(abstract_linear_mma_kernel,
                         cudaFuncAttributeMaxDynamicSharedMemorySize, DSMEM_BYTES);

    convert_x_kernel<<<(B_DIM * K_DIM) / (256 * 8), 256>>>(x);

    dim3 grid(OUT_DIM / BN, B_DIM / BM);  // (64, 2) = 128 CTAs
    abstract_linear_mma_kernel<<<grid, 256, DSMEM_BYTES>>>(low, high, W, bias,
                                                           y, low_out, high_out);
}

// round 16
// speedup vs baseline: 1.0014x; 1.0014x over previous
#include <cuda_runtime.h>
#include <cuda_bf16.h>
#include <cstdint>

#define K_DIM   8192
#define B_DIM   256
#define OUT_DIM 8192
#define BM      128
#define BN      128
#define KC      32
#define NT      (K_DIM / KC)          // 256 stages
#define RSTRIDE 80                    // bytes per smem row (32 bf16 + 16B pad)
#define SPLIT_BYTES (128 * RSTRIDE)   // 10240 per split tile
#define STAGE_BYTES (4 * SPLIT_BYTES) // A_hi|A_lo|B_hi|B_lo = 40960
#define NSTAGE  3
#define LH_OFF  (NSTAGE * STAGE_BYTES)        // 122880: low[8192] | high[8192]
#define DSMEM_BYTES (LH_OFF + 2 * K_DIM * 4)  // 188416

// ---------------- scratch: bf16 split of x ----------------
__device__ __nv_bfloat16 g_x_hi[(size_t)B_DIM * K_DIM];
__device__ __nv_bfloat16 g_x_lo[(size_t)B_DIM * K_DIM];

// ---------------- helpers ----------------
__device__ __forceinline__ uint32_t smem_u32(const void* p) {
    uint32_t a;
    asm("{ .reg .u64 t; cvta.to.shared.u64 t, %1; cvt.u32.u64 %0, t; }" : "=r"(a) : "l"(p));
    return a;
}
__device__ __forceinline__ uint32_t cvt2(float hiVal, float loVal) {
    uint32_t r;
    asm("cvt.rn.bf16x2.f32 %0, %1, %2;" : "=r"(r) : "f"(hiVal), "f"(loVal));
    return r;
}

#define LDSM4(r0, r1, r2, r3, addr) \
    asm volatile("ldmatrix.sync.aligned.m8n8.x4.shared.b16 {%0,%1,%2,%3}, [%4];" \
                 : "=r"(r0), "=r"(r1), "=r"(r2), "=r"(r3) : "r"(addr))

#define MMA(c, a, b) \
    asm volatile("mma.sync.aligned.m16n8k16.row.col.f32.bf16.bf16.f32 " \
                 "{%0,%1,%2,%3}, {%4,%5,%6,%7}, {%8,%9}, {%0,%1,%2,%3};" \
                 : "+f"((c)[0]), "+f"((c)[1]), "+f"((c)[2]), "+f"((c)[3]) \
                 : "r"((a)[0]), "r"((a)[1]), "r"((a)[2]), "r"((a)[3]), \
                   "r"((b)[0]), "r"((b)[1]))

#define CP_ASYNC16(dst, src) \
    asm volatile("cp.async.cg.shared.global [%0], [%1], 16;" :: "r"(dst), "l"(src) : "memory")
#define CP_COMMIT() asm volatile("cp.async.commit_group;" ::: "memory")
#define CP_WAIT1()  asm volatile("cp.async.wait_group 1;" ::: "memory")
#define CP_WAIT0()  asm volatile("cp.async.wait_group 0;" ::: "memory")

// ---------------- kernel 1: split x into bf16 hi/lo ----------------
__global__ __launch_bounds__(256)
void convert_x_kernel(const float* __restrict__ x) {
    size_t i = ((size_t)blockIdx.x * 256 + threadIdx.x) * 8;
    float4 a = *reinterpret_cast<const float4*>(x + i);
    float4 b = *reinterpret_cast<const float4*>(x + i + 4);
    uint32_t h0 = cvt2(a.y, a.x), h1 = cvt2(a.w, a.z);
    uint32_t h2 = cvt2(b.y, b.x), h3 = cvt2(b.w, b.z);
    float l0 = a.x - __uint_as_float(h0 << 16);
    float l1 = a.y - __uint_as_float(h0 & 0xffff0000u);
    float l2 = a.z - __uint_as_float(h1 << 16);
    float l3 = a.w - __uint_as_float(h1 & 0xffff0000u);
    float l4 = b.x - __uint_as_float(h2 << 16);
    float l5 = b.y - __uint_as_float(h2 & 0xffff0000u);
    float l6 = b.z - __uint_as_float(h3 << 16);
    float l7 = b.w - __uint_as_float(h3 & 0xffff0000u);
    *reinterpret_cast<uint4*>(g_x_hi + i) = make_uint4(h0, h1, h2, h3);
    *reinterpret_cast<uint4*>(g_x_lo + i) =
        make_uint4(cvt2(l1, l0), cvt2(l3, l2), cvt2(l5, l4), cvt2(l7, l6));
}

// ---------------- kernel 2: split-bf16 mma GEMM + fused IBP ----------------
__global__ __launch_bounds__(256, 1)
void abstract_linear_mma_kernel(const float* __restrict__ low,
                                const float* __restrict__ high,
                                const float* __restrict__ W,
                                const float* __restrict__ bias,
                                float* __restrict__ y,
                                float* __restrict__ low_out,
                                float* __restrict__ high_out)
{
    extern __shared__ __align__(128) char dsm[];
    const uint32_t sbase = smem_u32(dsm);

    const int tid  = threadIdx.x;
    const int lane = tid & 31;
    const int wid  = tid >> 5;       // 0..7
    const int nBase = blockIdx.x * BN;
    const int mBase = blockIdx.y * BM;
    const bool doB = (blockIdx.y == 0);

    const int wm = wid >> 2;   // 0..1  (m direction, 64 rows each)
    const int wn = wid & 3;    // 0..3  (n direction, 32 cols each)

    // ---- preload low/high into smem (used by doB CTAs) ----
    float* s_low  = reinterpret_cast<float*>(dsm + LH_OFF);
    float* s_high = s_low + K_DIM;
    if (doB) {
        #pragma unroll
        for (int i = 0; i < 8; ++i) {
            const int idx = (tid + i * 256) * 4;
            *reinterpret_cast<float4*>(s_low + idx)  = *reinterpret_cast<const float4*>(low + idx);
            *reinterpret_cast<float4*>(s_high + idx) = *reinterpret_cast<const float4*>(high + idx);
        }
    }
    __syncthreads();   // preload visible before first stashW (race fix)

    // ---- x loader (cp.async): thread -> (split, row): 64B per thread ----
    const int xrow = tid & 127;
    const bool isHi = (tid < 128);
    const __nv_bfloat16* xg = (isHi ? g_x_hi : g_x_lo) + (size_t)(mBase + xrow) * K_DIM;
    const uint32_t xdstBase = (isHi ? 0u : (uint32_t)SPLIT_BYTES) + (uint32_t)xrow * RSTRIDE;

    // ---- W loader: thread -> (row, 16-elem k half) ----
    const int wrow = tid >> 1;        // 0..127
    const int lkh  = tid & 1;         // k half (16 elems)
    const float* wg = W + (size_t)(nBase + wrow) * K_DIM + lkh * 16;
    const uint32_t wsts = (uint32_t)wrow * RSTRIDE + lkh * 32;

    // ---- ldmatrix per-thread offsets ----
    const uint32_t aOff = (uint32_t)(wm * 64 + (lane & 15)) * RSTRIDE + (lane >> 4) * 16;
    const uint32_t bOff = (uint32_t)(wn * 32 + (lane & 7) + ((lane >> 4) & 1) * 8) * RSTRIDE
                        + ((lane >> 3) & 1) * 16;

    float acc[4][4][4];
    #pragma unroll
    for (int i = 0; i < 4; ++i)
        #pragma unroll
        for (int j = 0; j < 4; ++j)
            #pragma unroll
            for (int r = 0; r < 4; ++r) acc[i][j][r] = 0.f;

    float boundLo = 0.f, boundHi = 0.f;
    float4 wv[2][4];   // double-buffered: loadW issues before stashW consumes

    auto cpX = [&](int stage, int kt) {
        const uint32_t dst = sbase + stage * STAGE_BYTES + xdstBase;
        const __nv_bfloat16* src = xg + kt * KC;
        CP_ASYNC16(dst,      src);
        CP_ASYNC16(dst + 16, src + 8);
        CP_ASYNC16(dst + 32, src + 16);
        CP_ASYNC16(dst + 48, src + 24);
        CP_COMMIT();
    };

    auto loadW = [&](int kt, int buf) {
        #pragma unroll
        for (int i = 0; i < 4; ++i)
            wv[buf][i] = *reinterpret_cast<const float4*>(wg + (size_t)kt * KC + i * 4);
    };

    auto stashW = [&](int stage, int kt, int buf) {
        char* bHp = dsm + (size_t)stage * STAGE_BYTES + 2 * SPLIT_BYTES + wsts;
        char* bLp = bHp + SPLIT_BYTES;
        #pragma unroll
        for (int i = 0; i < 2; ++i) {
            const float4 a = wv[buf][2 * i], b = wv[buf][2 * i + 1];
            uint32_t h0 = cvt2(a.y, a.x), h1 = cvt2(a.w, a.z);
            uint32_t h2 = cvt2(b.y, b.x), h3 = cvt2(b.w, b.z);
            float l0 = a.x - __uint_as_float(h0 << 16);
            float l1 = a.y - __uint_as_float(h0 & 0xffff0000u);
            float l2 = a.z - __uint_as_float(h1 << 16);
            float l3 = a.w - __uint_as_float(h1 & 0xffff0000u);
            float l4 = b.x - __uint_as_float(h2 << 16);
            float l5 = b.y - __uint_as_float(h2 & 0xffff0000u);
            float l6 = b.z - __uint_as_float(h3 << 16);
            float l7 = b.w - __uint_as_float(h3 & 0xffff0000u);
            *reinterpret_cast<uint4*>(bHp + i * 16) = make_uint4(h0, h1, h2, h3);
            *reinterpret_cast<uint4*>(bLp + i * 16) =
                make_uint4(cvt2(l1, l0), cvt2(l3, l2), cvt2(l5, l4), cvt2(l7, l6));
            if (doB) {
                const float* lp = s_low  + kt * KC + lkh * 16 + i * 8;
                const float* hp = s_high + kt * KC + lkh * 16 + i * 8;
                const float4 la = *reinterpret_cast<const float4*>(lp);
                const float4 lb = *reinterpret_cast<const float4*>(lp + 4);
                const float4 ha = *reinterpret_cast<const float4*>(hp);
                const float4 hb = *reinterpret_cast<const float4*>(hp + 4);
                float p, q;
                p = a.x * la.x; q = a.x * ha.x; boundLo += fminf(p, q); boundHi += fmaxf(p, q);
                p = a.y * la.y; q = a.y * ha.y; boundLo += fminf(p, q); boundHi += fmaxf(p, q);
                p = a.z * la.z; q = a.z * ha.z; boundLo += fminf(p, q); boundHi += fmaxf(p, q);
                p = a.w * la.w; q = a.w * ha.w; boundLo += fminf(p, q); boundHi += fmaxf(p, q);
                p = b.x * lb.x; q = b.x * hb.x; boundLo += fminf(p, q); boundHi += fmaxf(p, q);
                p = b.y * lb.y; q = b.y * hb.y; boundLo += fminf(p, q); boundHi += fmaxf(p, q);
                p = b.z * lb.z; q = b.z * hb.z; boundLo += fminf(p, q); boundHi += fmaxf(p, q);
                p = b.w * lb.w; q = b.w * hb.w; boundLo += fminf(p, q); boundHi += fmaxf(p, q);
            }
        }
    };

    // ---- doMMA: R14 champion version (single k16 fragment set) ----
    auto doMMA = [&](int stage) {
        const uint32_t A_hi = sbase + stage * STAGE_BYTES;
        const uint32_t A_lo = A_hi + SPLIT_BYTES;
        const uint32_t B_hi = A_hi + 2 * SPLIT_BYTES;
        const uint32_t B_lo = A_hi + 3 * SPLIT_BYTES;
        #pragma unroll
        for (int k16 = 0; k16 < 2; ++k16) {
            uint32_t aH[4][4], aL[4][4], bH[4][2], bL[4][2];
            #pragma unroll
            for (int mf = 0; mf < 4; ++mf) {
                LDSM4(aH[mf][0], aH[mf][1], aH[mf][2], aH[mf][3],
                      A_hi + aOff + mf * (16 * RSTRIDE) + k16 * 32);
                LDSM4(aL[mf][0], aL[mf][1], aL[mf][2], aL[mf][3],
                      A_lo + aOff + mf * (16 * RSTRIDE) + k16 * 32);
            }
            #pragma unroll
            for (int p = 0; p < 2; ++p) {
                uint32_t r0, r1, r2, r3;
                LDSM4(r0, r1, r2, r3, B_hi + bOff + p * (16 * RSTRIDE) + k16 * 32);
                bH[2 * p][0] = r0; bH[2 * p][1] = r1;
                bH[2 * p + 1][0] = r2; bH[2 * p + 1][1] = r3;
                LDSM4(r0, r1, r2, r3, B_lo + bOff + p * (16 * RSTRIDE) + k16 * 32);
                bL[2 * p][0] = r0; bL[2 * p][1] = r1;
                bL[2 * p + 1][0] = r2; bL[2 * p + 1][1] = r3;
            }
            // term-major: 16 independent MMAs between accumulator reuses
            #pragma unroll
            for (int mf = 0; mf < 4; ++mf)
                #pragma unroll
                for (int nf = 0; nf < 4; ++nf) MMA(acc[mf][nf], aH[mf], bH[nf]);
            #pragma unroll
            for (int mf = 0; mf < 4; ++mf)
                #pragma unroll
                for (int nf = 0; nf < 4; ++nf) MMA(acc[mf][nf], aH[mf], bL[nf]);
            #pragma unroll
            for (int mf = 0; mf < 4; ++mf)
                #pragma unroll
                for (int nf = 0; nf < 4; ++nf) MMA(acc[mf][nf], aL[mf], bH[nf]);
        }
    };

    // ---- prologue ----
    cpX(0, 0);
    cpX(1, 1);
    loadW(0, 0);
    stashW(0, 0, 0);
    loadW(1, 1);
    CP_WAIT1();
    __syncthreads();

    // ---- main loop: cp(kt+2) -> loadW(kt+2) -> stash(kt+1) -> MMA(kt) ----
    #pragma unroll 1
    for (int kt = 0; kt < NT; ++kt) {
        const int stage = kt % NSTAGE;
        const int cur  = (kt + 1) & 1;   // wv buffer holding W(kt+1)
        const int nxt  = kt & 1;         // wv buffer to receive W(kt+2)
        if (kt + 2 < NT) {
            cpX((kt + 2) % NSTAGE, kt + 2);   // async x: issue first
            loadW(kt + 2, nxt);               // W LDG issues before stash block
        }
        if (kt + 1 < NT) stashW((kt + 1) % NSTAGE, kt + 1, cur);
        doMMA(stage);
        if (kt + 2 < NT) { CP_WAIT1(); } else { CP_WAIT0(); }
        __syncthreads();
    }

    // ---- epilogue: y = acc + bias ----
    #pragma unroll
    for (int mf = 0; mf < 4; ++mf) {
        const int r0 = mBase + wm * 64 + mf * 16 + (lane >> 2);
        #pragma unroll
        for (int nf = 0; nf < 4; ++nf) {
            const int c = nBase + wn * 32 + nf * 8 + (lane & 3) * 2;
            const float2 bv = *reinterpret_cast<const float2*>(bias + c);
            float2 o0 = make_float2(acc[mf][nf][0] + bv.x, acc[mf][nf][1] + bv.y);
            float2 o1 = make_float2(acc[mf][nf][2] + bv.x, acc[mf][nf][3] + bv.y);
            *reinterpret_cast<float2*>(y + (size_t)r0 * OUT_DIM + c) = o0;
            *reinterpret_cast<float2*>(y + (size_t)(r0 + 8) * OUT_DIM + c) = o1;
        }
    }

    // ---- epilogue: bounds (width-2 deterministic reduction) ----
    if (doB) {
        boundLo += __shfl_xor_sync(0xffffffffu, boundLo, 1);
        boundHi += __shfl_xor_sync(0xffffffffu, boundHi, 1);
        if (lkh == 0) {
            const int r = nBase + wrow;
            const float bb = bias[r];
            low_out[r]  = boundLo + bb;
            high_out[r] = boundHi + bb;
        }
    }
}

extern "C" void kernel_launch(void* const* d_in, const int* in_sizes, int n_in,
                              void* d_out, int out_size) {
    const float* x    = (const float*)d_in[0];
    const float* low  = (const float*)d_in[1];
    const float* high = (const float*)d_in[2];
    const float* W    = (const float*)d_in[3];
    const float* bias = (const float*)d_in[4];

    float* y        = (float*)d_out;
    float* low_out  = y + (size_t)B_DIM * OUT_DIM;
    float* high_out = low_out + OUT_DIM;

    cudaFuncSetAttribute(abstract_linear_mma_kernel,
                         cudaFuncAttributeMaxDynamicSharedMemorySize, DSMEM_BYTES);

    convert_x_kernel<<<(B_DIM * K_DIM) / (256 * 8), 256>>>(x);

    dim3 grid(OUT_DIM / BN, B_DIM / BM);  // (64, 2) = 128 CTAs
    abstract_linear_mma_kernel<<<grid, 256, DSMEM_BYTES>>>(low, high, W, bias,
                                                           y, low_out, high_out);
}

// round 17
// speedup vs baseline: 1.2765x; 1.2747x over previous
#include <cuda_runtime.h>
#include <cuda_bf16.h>
#include <cstdint>

#define K_DIM   8192
#define B_DIM   256
#define OUT_DIM 8192
#define BM      128
#define BN      128
#define KC      32
#define NT      (K_DIM / KC)          // 256 stages
#define RSTRIDE 80                    // bytes per smem row (32 bf16 + 16B pad)
#define SPLIT_BYTES (128 * RSTRIDE)   // 10240 per split tile
#define STAGE_BYTES (4 * SPLIT_BYTES) // A_hi|A_lo|B_hi|B_lo = 40960
#define NSTAGE  3
#define LH_OFF  (NSTAGE * STAGE_BYTES)        // 122880: low[8192] | high[8192]
#define DSMEM_BYTES (LH_OFF + 2 * K_DIM * 4)  // 188416

// ---------------- scratch: bf16 split of x ----------------
__device__ __nv_bfloat16 g_x_hi[(size_t)B_DIM * K_DIM];
__device__ __nv_bfloat16 g_x_lo[(size_t)B_DIM * K_DIM];

// ---------------- helpers ----------------
__device__ __forceinline__ uint32_t smem_u32(const void* p) {
    uint32_t a;
    asm("{ .reg .u64 t; cvta.to.shared.u64 t, %1; cvt.u32.u64 %0, t; }" : "=r"(a) : "l"(p));
    return a;
}
__device__ __forceinline__ uint32_t cvt2(float hiVal, float loVal) {
    uint32_t r;
    asm("cvt.rn.bf16x2.f32 %0, %1, %2;" : "=r"(r) : "f"(hiVal), "f"(loVal));
    return r;
}

#define LDSM4(r0, r1, r2, r3, addr) \
    asm volatile("ldmatrix.sync.aligned.m8n8.x4.shared.b16 {%0,%1,%2,%3}, [%4];" \
                 : "=r"(r0), "=r"(r1), "=r"(r2), "=r"(r3) : "r"(addr))

#define MMA(c, a, b) \
    asm volatile("mma.sync.aligned.m16n8k16.row.col.f32.bf16.bf16.f32 " \
                 "{%0,%1,%2,%3}, {%4,%5,%6,%7}, {%8,%9}, {%0,%1,%2,%3};" \
                 : "+f"((c)[0]), "+f"((c)[1]), "+f"((c)[2]), "+f"((c)[3]) \
                 : "r"((a)[0]), "r"((a)[1]), "r"((a)[2]), "r"((a)[3]), \
                   "r"((b)[0]), "r"((b)[1]))

#define CP_ASYNC16(dst, src) \
    asm volatile("cp.async.cg.shared.global [%0], [%1], 16;" :: "r"(dst), "l"(src) : "memory")
#define CP_COMMIT() asm volatile("cp.async.commit_group;" ::: "memory")
#define CP_WAIT1()  asm volatile("cp.async.wait_group 1;" ::: "memory")
#define CP_WAIT0()  asm volatile("cp.async.wait_group 0;" ::: "memory")

// ---------------- kernel 1: split x into bf16 hi/lo ----------------
__global__ __launch_bounds__(256)
void convert_x_kernel(const float* __restrict__ x) {
    size_t i = ((size_t)blockIdx.x * 256 + threadIdx.x) * 8;
    float4 a = *reinterpret_cast<const float4*>(x + i);
    float4 b = *reinterpret_cast<const float4*>(x + i + 4);
    uint32_t h0 = cvt2(a.y, a.x), h1 = cvt2(a.w, a.z);
    uint32_t h2 = cvt2(b.y, b.x), h3 = cvt2(b.w, b.z);
    float l0 = a.x - __uint_as_float(h0 << 16);
    float l1 = a.y - __uint_as_float(h0 & 0xffff0000u);
    float l2 = a.z - __uint_as_float(h1 << 16);
    float l3 = a.w - __uint_as_float(h1 & 0xffff0000u);
    float l4 = b.x - __uint_as_float(h2 << 16);
    float l5 = b.y - __uint_as_float(h2 & 0xffff0000u);
    float l6 = b.z - __uint_as_float(h3 << 16);
    float l7 = b.w - __uint_as_float(h3 & 0xffff0000u);
    *reinterpret_cast<uint4*>(g_x_hi + i) = make_uint4(h0, h1, h2, h3);
    *reinterpret_cast<uint4*>(g_x_lo + i) =
        make_uint4(cvt2(l1, l0), cvt2(l3, l2), cvt2(l5, l4), cvt2(l7, l6));
}

// ---------------- kernel 2: split-bf16 mma GEMM + fused IBP ----------------
__global__ __launch_bounds__(256, 1)
void abstract_linear_mma_kernel(const float* __restrict__ low,
                                const float* __restrict__ high,
                                const float* __restrict__ W,
                                const float* __restrict__ bias,
                                float* __restrict__ y,
                                float* __restrict__ low_out,
                                float* __restrict__ high_out)
{
    extern __shared__ __align__(128) char dsm[];
    const uint32_t sbase = smem_u32(dsm);

    const int tid  = threadIdx.x;
    const int lane = tid & 31;
    const int wid  = tid >> 5;       // 0..7
    const int nBase = blockIdx.x * BN;
    const int mBase = blockIdx.y * BM;
    const bool doB = (blockIdx.y == 0);

    const int wm = wid >> 2;   // 0..1  (m direction, 64 rows each)
    const int wn = wid & 3;    // 0..3  (n direction, 32 cols each)

    // ---- preload low/high into smem (used by doB CTAs) ----
    float* s_low  = reinterpret_cast<float*>(dsm + LH_OFF);
    float* s_high = s_low + K_DIM;
    if (doB) {
        #pragma unroll
        for (int i = 0; i < 8; ++i) {
            const int idx = (tid + i * 256) * 4;
            *reinterpret_cast<float4*>(s_low + idx)  = *reinterpret_cast<const float4*>(low + idx);
            *reinterpret_cast<float4*>(s_high + idx) = *reinterpret_cast<const float4*>(high + idx);
        }
    }
    __syncthreads();   // preload visible before first stashW (race fix)

    // ---- x loader (cp.async): thread -> (split, row): 64B per thread ----
    const int xrow = tid & 127;
    const bool isHi = (tid < 128);
    const __nv_bfloat16* xg = (isHi ? g_x_hi : g_x_lo) + (size_t)(mBase + xrow) * K_DIM;
    const uint32_t xdstBase = (isHi ? 0u : (uint32_t)SPLIT_BYTES) + (uint32_t)xrow * RSTRIDE;

    // ---- W loader: thread -> (row, 16-elem k half) ----
    const int wrow = tid >> 1;        // 0..127
    const int lkh  = tid & 1;         // k half (16 elems)
    const float* wg = W + (size_t)(nBase + wrow) * K_DIM + lkh * 16;
    const uint32_t wsts = (uint32_t)wrow * RSTRIDE + lkh * 32;

    // ---- ldmatrix per-thread offsets ----
    const uint32_t aOff = (uint32_t)(wm * 64 + (lane & 15)) * RSTRIDE + (lane >> 4) * 16;
    const uint32_t bOff = (uint32_t)(wn * 32 + (lane & 7) + ((lane >> 4) & 1) * 8) * RSTRIDE
                        + ((lane >> 3) & 1) * 16;

    float acc[4][4][4];
    #pragma unroll
    for (int i = 0; i < 4; ++i)
        #pragma unroll
        for (int j = 0; j < 4; ++j)
            #pragma unroll
            for (int r = 0; r < 4; ++r) acc[i][j][r] = 0.f;

    float boundLo = 0.f, boundHi = 0.f;
    float4 wv[4];   // single register buffer (R14 champion config)

    auto cpX = [&](int stage, int kt) {
        const uint32_t dst = sbase + stage * STAGE_BYTES + xdstBase;
        const __nv_bfloat16* src = xg + kt * KC;
        CP_ASYNC16(dst,      src);
        CP_ASYNC16(dst + 16, src + 8);
        CP_ASYNC16(dst + 32, src + 16);
        CP_ASYNC16(dst + 48, src + 24);
        CP_COMMIT();
    };

    auto loadW = [&](int kt) {
        #pragma unroll
        for (int i = 0; i < 4; ++i)
            wv[i] = *reinterpret_cast<const float4*>(wg + (size_t)kt * KC + i * 4);
    };

    auto stashW = [&](int stage, int kt) {
        char* bHp = dsm + (size_t)stage * STAGE_BYTES + 2 * SPLIT_BYTES + wsts;
        char* bLp = bHp + SPLIT_BYTES;
        #pragma unroll
        for (int i = 0; i < 2; ++i) {
            const float4 a = wv[2 * i], b = wv[2 * i + 1];
            uint32_t h0 = cvt2(a.y, a.x), h1 = cvt2(a.w, a.z);
            uint32_t h2 = cvt2(b.y, b.x), h3 = cvt2(b.w, b.z);
            float l0 = a.x - __uint_as_float(h0 << 16);
            float l1 = a.y - __uint_as_float(h0 & 0xffff0000u);
            float l2 = a.z - __uint_as_float(h1 << 16);
            float l3 = a.w - __uint_as_float(h1 & 0xffff0000u);
            float l4 = b.x - __uint_as_float(h2 << 16);
            float l5 = b.y - __uint_as_float(h2 & 0xffff0000u);
            float l6 = b.z - __uint_as_float(h3 << 16);
            float l7 = b.w - __uint_as_float(h3 & 0xffff0000u);
            *reinterpret_cast<uint4*>(bHp + i * 16) = make_uint4(h0, h1, h2, h3);
            *reinterpret_cast<uint4*>(bLp + i * 16) =
                make_uint4(cvt2(l1, l0), cvt2(l3, l2), cvt2(l5, l4), cvt2(l7, l6));
            if (doB) {
                const float* lp = s_low  + kt * KC + lkh * 16 + i * 8;
                const float* hp = s_high + kt * KC + lkh * 16 + i * 8;
                const float4 la = *reinterpret_cast<const float4*>(lp);
                const float4 lb = *reinterpret_cast<const float4*>(lp + 4);
                const float4 ha = *reinterpret_cast<const float4*>(hp);
                const float4 hb = *reinterpret_cast<const float4*>(hp + 4);
                float p, q;
                p = a.x * la.x; q = a.x * ha.x; boundLo += fminf(p, q); boundHi += fmaxf(p, q);
                p = a.y * la.y; q = a.y * ha.y; boundLo += fminf(p, q); boundHi += fmaxf(p, q);
                p = a.z * la.z; q = a.z * ha.z; boundLo += fminf(p, q); boundHi += fmaxf(p, q);
                p = a.w * la.w; q = a.w * ha.w; boundLo += fminf(p, q); boundHi += fmaxf(p, q);
                p = b.x * lb.x; q = b.x * hb.x; boundLo += fminf(p, q); boundHi += fmaxf(p, q);
                p = b.y * lb.y; q = b.y * hb.y; boundLo += fminf(p, q); boundHi += fmaxf(p, q);
                p = b.z * lb.z; q = b.z * hb.z; boundLo += fminf(p, q); boundHi += fmaxf(p, q);
                p = b.w * lb.w; q = b.w * hb.w; boundLo += fminf(p, q); boundHi += fmaxf(p, q);
            }
        }
    };

    auto doMMA = [&](int stage) {
        const uint32_t A_hi = sbase + stage * STAGE_BYTES;
        const uint32_t A_lo = A_hi + SPLIT_BYTES;
        const uint32_t B_hi = A_hi + 2 * SPLIT_BYTES;
        const uint32_t B_lo = A_hi + 3 * SPLIT_BYTES;
        #pragma unroll
        for (int k16 = 0; k16 < 2; ++k16) {
            uint32_t aH[4][4], aL[4][4], bH[4][2], bL[4][2];
            #pragma unroll
            for (int mf = 0; mf < 4; ++mf) {
                LDSM4(aH[mf][0], aH[mf][1], aH[mf][2], aH[mf][3],
                      A_hi + aOff + mf * (16 * RSTRIDE) + k16 * 32);
                LDSM4(aL[mf][0], aL[mf][1], aL[mf][2], aL[mf][3],
                      A_lo + aOff + mf * (16 * RSTRIDE) + k16 * 32);
            }
            #pragma unroll
            for (int p = 0; p < 2; ++p) {
                uint32_t r0, r1, r2, r3;
                LDSM4(r0, r1, r2, r3, B_hi + bOff + p * (16 * RSTRIDE) + k16 * 32);
                bH[2 * p][0] = r0; bH[2 * p][1] = r1;
                bH[2 * p + 1][0] = r2; bH[2 * p + 1][1] = r3;
                LDSM4(r0, r1, r2, r3, B_lo + bOff + p * (16 * RSTRIDE) + k16 * 32);
                bL[2 * p][0] = r0; bL[2 * p][1] = r1;
                bL[2 * p + 1][0] = r2; bL[2 * p + 1][1] = r3;
            }
            // term-major: 16 independent MMAs between accumulator reuses
            #pragma unroll
            for (int mf = 0; mf < 4; ++mf)
                #pragma unroll
                for (int nf = 0; nf < 4; ++nf) MMA(acc[mf][nf], aH[mf], bH[nf]);
            #pragma unroll
            for (int mf = 0; mf < 4; ++mf)
                #pragma unroll
                for (int nf = 0; nf < 4; ++nf) MMA(acc[mf][nf], aH[mf], bL[nf]);
            #pragma unroll
            for (int mf = 0; mf < 4; ++mf)
                #pragma unroll
                for (int nf = 0; nf < 4; ++nf) MMA(acc[mf][nf], aL[mf], bH[nf]);
        }
    };

    // ---- prologue: x stages 0,1 in flight; W stage 0 stashed; W stage 1 in regs ----
    cpX(0, 0);
    cpX(1, 1);
    loadW(0);
    stashW(0, 0);
    loadW(1);
    CP_WAIT1();
    __syncthreads();

    // ---- main loop: stash(kt+1) -> cp/load(kt+2) -> MMA(kt)  (R14 champion order) ----
    #pragma unroll 1
    for (int kt = 0; kt < NT; ++kt) {
        const int stage = kt % NSTAGE;
        if (kt + 1 < NT) stashW((kt + 1) % NSTAGE, kt + 1);   // W regs from prev iter
        if (kt + 2 < NT) {
            cpX((kt + 2) % NSTAGE, kt + 2);
            loadW(kt + 2);                                     // full stage to land
        }
        doMMA(stage);
        if (kt + 2 < NT) { CP_WAIT1(); } else { CP_WAIT0(); }
        __syncthreads();
    }

    // ---- epilogue: y = acc + bias ----
    #pragma unroll
    for (int mf = 0; mf < 4; ++mf) {
        const int r0 = mBase + wm * 64 + mf * 16 + (lane >> 2);
        #pragma unroll
        for (int nf = 0; nf < 4; ++nf) {
            const int c = nBase + wn * 32 + nf * 8 + (lane & 3) * 2;
            const float2 bv = *reinterpret_cast<const float2*>(bias + c);
            float2 o0 = make_float2(acc[mf][nf][0] + bv.x, acc[mf][nf][1] + bv.y);
            float2 o1 = make_float2(acc[mf][nf][2] + bv.x, acc[mf][nf][3] + bv.y);
            *reinterpret_cast<float2*>(y + (size_t)r0 * OUT_DIM + c) = o0;
            *reinterpret_cast<float2*>(y + (size_t)(r0 + 8) * OUT_DIM + c) = o1;
        }
    }

    // ---- epilogue: bounds (width-2 deterministic reduction) ----
    if (doB) {
        boundLo += __shfl_xor_sync(0xffffffffu, boundLo, 1);
        boundHi += __shfl_xor_sync(0xffffffffu, boundHi, 1);
        if (lkh == 0) {
            const int r = nBase + wrow;
            const float bb = bias[r];
            low_out[r]  = boundLo + bb;
            high_out[r] = boundHi + bb;
        }
    }
}

extern "C" void kernel_launch(void* const* d_in, const int* in_sizes, int n_in,
                              void* d_out, int out_size) {
    const float* x    = (const float*)d_in[0];
    const float* low  = (const float*)d_in[1];
    const float* high = (const float*)d_in[2];
    const float* W    = (const float*)d_in[3];
    const float* bias = (const float*)d_in[4];

    float* y        = (float*)d_out;
    float* low_out  = y + (size_t)B_DIM * OUT_DIM;
    float* high_out = low_out + OUT_DIM;

    cudaFuncSetAttribute(abstract_linear_mma_kernel,
                         cudaFuncAttributeMaxDynamicSharedMemorySize, DSMEM_BYTES);

    convert_x_kernel<<<(B_DIM * K_DIM) / (256 * 8), 256>>>(x);

    dim3 grid(OUT_DIM / BN, B_DIM / BM);  // (64, 2) = 128 CTAs
    abstract_linear_mma_kernel<<<grid, 256, DSMEM_BYTES>>>(low, high, W, bias,
                                                           y, low_out, high_out);
}